// round 4
// baseline (speedup 1.0000x reference)
#include <cuda_runtime.h>

// ---------------------------------------------------------------------------
// SparseConv2D reduction: the block-gather + SAME-conv + interior-crop in the
// reference is exactly a dense VALID 3x3 conv:
//   out[n,r,c,co] = sum_{dr,dc,ci} x[n,r+dr,c+dc,ci] * K[dr,dc,ci,co] + bias
// for r,c in [0,504), multiplied by active[n, r/14, c/14] where
//   active = (max over the block's 16x16 mask window) > 0.5.
// ---------------------------------------------------------------------------

#define NIMG 8
#define HH   506
#define WW   506
#define OH   504
#define OW   504
#define NBH  36
#define NBW  36

// conv tiling
#define TR 16            // output rows per CTA
#define TC 32            // output cols per CTA
#define XROWS 18         // x rows needed (TR+2)
#define XCOLS 34         // x cols needed (TC+2)
#define XRS   36         // smem row stride (floats)
#define XPS   652        // smem plane stride (floats): mult of 4 (aligned LDS.128),
                         // 652 % 32 == 12 -> only 4-way STS conflict on transpose
#define SMEM_XF (32 * XPS)   // 20864 floats
#define SMEM_KF 9216         // 3*3*32*32 weights
#define SMEM_BYTES ((SMEM_XF + SMEM_KF) * 4)  // 120320 B

__device__ float d_active[NIMG * NBH * NBW];

// ---------------------------------------------------------------------------
// Kernel 1: per-(n,bi,bj) active flags. One warp per block-index; warp
// max-reduces the 16x16 mask window.
// ---------------------------------------------------------------------------
__global__ void __launch_bounds__(256)
active_kernel(const float* __restrict__ mask) {
    int w    = blockIdx.x * 8 + (threadIdx.x >> 5);   // warp id = flat (n,bi,bj)
    int lane = threadIdx.x & 31;
    int n    = w / (NBH * NBW);
    int rem  = w - n * (NBH * NBW);
    int bi   = rem / NBW;
    int bj   = rem - bi * NBW;

    float m = -1e30f;
#pragma unroll
    for (int i = 0; i < 8; i++) {
        int e  = lane + 32 * i;        // 0..255 over the 16x16 window
        int rr = e >> 4;
        int cc = e & 15;
        m = fmaxf(m, mask[(n * HH + bi * 14 + rr) * WW + (bj * 14 + cc)]);
    }
#pragma unroll
    for (int off = 16; off; off >>= 1)
        m = fmaxf(m, __shfl_xor_sync(0xffffffffu, m, off));
    if (lane == 0)
        d_active[w] = (m > 0.5f) ? 1.0f : 0.0f;
}

// ---------------------------------------------------------------------------
// Kernel 2: dense 3x3 valid conv, register-blocked 8 pixels x 8 couts/thread.
// CTA = 16x32 output pixels x 32 couts, 256 threads.
//   thread t: cout group g = t&3 (co base g*8)
//             pixel group p = t>>2: pr = p>>2 (row 0..15), pc = (p&3)*8
// x tile in smem channel-major [ci][row][col] so 8+shift pixel values come
// from 3 aligned LDS.128 per (dr,ci), reused across dc=0..2.
// ---------------------------------------------------------------------------
extern __shared__ float smem[];

__global__ void __launch_bounds__(256, 1)
conv_kernel(const float* __restrict__ x, const float* __restrict__ kern,
            const float* __restrict__ bias, float* __restrict__ out) {
    float* sx = smem;
    float* sk = smem + SMEM_XF;
    const int tid = threadIdx.x;
    const int n  = blockIdx.z;
    const int r0 = blockIdx.y * TR;
    const int c0 = blockIdx.x * TC;

    // ---- load x tile (transpose NHWC -> [ci][r][c]), zero-fill OOB ----
    const int TOT = XROWS * XCOLS * 32;   // 19584
    for (int e = tid; e < TOT; e += 256) {
        int ci = e & 31;
        int t2 = e >> 5;
        int c  = t2 % XCOLS;
        int r  = t2 / XCOLS;
        int h = r0 + r, w = c0 + c;
        float v = 0.0f;
        if (h < HH && w < WW)
            v = x[((n * HH + h) * WW + w) * 32 + ci];
        sx[ci * XPS + r * XRS + c] = v;
    }
    // ---- load weights [dr][dc][ci][co] verbatim ----
    for (int e = tid; e < SMEM_KF; e += 256)
        sk[e] = kern[e];
    __syncthreads();

    const int g   = tid & 3;
    const int co0 = g * 8;
    const int p   = tid >> 2;
    const int pr  = p >> 2;
    const int pc  = (p & 3) * 8;

    float bs[8];
#pragma unroll
    for (int j = 0; j < 8; j++) bs[j] = bias[co0 + j];

    float acc[8][8];
#pragma unroll
    for (int k = 0; k < 8; k++)
#pragma unroll
        for (int j = 0; j < 8; j++) acc[k][j] = bs[j];

#pragma unroll
    for (int dr = 0; dr < 3; dr++) {
        const float* xrow = sx + (pr + dr) * XRS + pc;
        const float* kr   = sk + dr * 3072 + co0;     // dr*3*32*32
#pragma unroll 2
        for (int ci = 0; ci < 32; ci++) {
            const float* xp = xrow + ci * XPS;
            float4 xa = *(const float4*)(xp + 0);
            float4 xb = *(const float4*)(xp + 4);
            float4 xc = *(const float4*)(xp + 8);
            float xbuf[12] = {xa.x, xa.y, xa.z, xa.w,
                              xb.x, xb.y, xb.z, xb.w,
                              xc.x, xc.y, xc.z, xc.w};
#pragma unroll
            for (int dc = 0; dc < 3; dc++) {
                const float* kp = kr + (dc * 32 + ci) * 32;
                float4 wa = *(const float4*)(kp);
                float4 wb = *(const float4*)(kp + 4);
                float wv[8] = {wa.x, wa.y, wa.z, wa.w,
                               wb.x, wb.y, wb.z, wb.w};
#pragma unroll
                for (int k = 0; k < 8; k++) {
                    float xv = xbuf[k + dc];
#pragma unroll
                    for (int j = 0; j < 8; j++)
                        acc[k][j] += xv * wv[j];
                }
            }
        }
    }

    // ---- store: apply per-14x14-block active flag, vectorized 2x float4 ----
    const int r = r0 + pr;
    if (r < OH) {
        const float* act = d_active + n * (NBH * NBW) + (r / 14) * NBW;
#pragma unroll
        for (int k = 0; k < 8; k++) {
            int c = c0 + pc + k;
            if (c < OW) {
                float f = act[c / 14];
                float* op = out + ((n * OH + r) * OW + c) * 32 + co0;
                float4 v0 = make_float4(acc[k][0] * f, acc[k][1] * f,
                                        acc[k][2] * f, acc[k][3] * f);
                float4 v1 = make_float4(acc[k][4] * f, acc[k][5] * f,
                                        acc[k][6] * f, acc[k][7] * f);
                *(float4*)(op)     = v0;
                *(float4*)(op + 4) = v1;
            }
        }
    }
}

// ---------------------------------------------------------------------------
// Launch: inputs in metadata order: x, mask, kernel, bias. Output float32.
// ---------------------------------------------------------------------------
extern "C" void kernel_launch(void* const* d_in, const int* in_sizes, int n_in,
                              void* d_out, int out_size) {
    const float* x    = (const float*)d_in[0];
    const float* mask = (const float*)d_in[1];
    const float* kern = (const float*)d_in[2];
    const float* bias = (const float*)d_in[3];
    float* out = (float*)d_out;

    // 8*36*36 = 10368 warps -> 1296 blocks of 8 warps
    active_kernel<<<1296, 256>>>(mask);

    cudaFuncSetAttribute(conv_kernel,
                         cudaFuncAttributeMaxDynamicSharedMemorySize,
                         SMEM_BYTES);
    dim3 grid((OW + TC - 1) / TC,    // 16
              (OH + TR - 1) / TR,    // 32
              NIMG);                 // 8
    conv_kernel<<<grid, 256, SMEM_BYTES>>>(x, kern, bias, out);
}

// round 6
// speedup vs baseline: 3.2565x; 3.2565x over previous
#include <cuda_runtime.h>
#include <cstdint>

// ---------------------------------------------------------------------------
// SparseConv2D == dense VALID 3x3 conv (R3 derivation, verified passing) times
// per-14x14-block active flag.  Tensor path: warp-level mma.sync tf32
// (sm_80+ baseline feature -- harness PTX target is plain sm_103, so no
// tcgen05).  Implicit GEMM: D[px,cout] += A[px,ci] * B[ci,cout] over 9 taps.
// ---------------------------------------------------------------------------

#define NIMG 8
#define HIN  506
#define WIN  506
#define CIN  32
#define OHW  504
#define NB   36

#define TROWS 8               // output rows per CTA (8 warps, 1 row each)
#define TCOLS 32              // output cols per CTA (warp m = 32)
#define XR    10              // input rows in tile
#define XC    34              // input cols in tile
#define PXF   36              // floats per pixel slot (stride/4 odd -> no conflicts)
#define XS_FLOATS (XR * XC * PXF)             // 12240
#define W_OFF     (XS_FLOATS * 4)             // 48960 bytes
#define SMEM_BYTES (W_OFF + 9 * 4096)         // 85824 bytes -> 2 CTAs/SM

__device__ float d_active[NIMG * NB * NB];

// ------------------------------ helpers ------------------------------------
__device__ __forceinline__ uint32_t cvt_tf32(float f){
    uint32_t u; asm("cvt.rna.tf32.f32 %0, %1;" : "=r"(u) : "f"(f)); return u;
}
__device__ __forceinline__ void mma8(float* c,
                                     uint32_t a0, uint32_t a1, uint32_t a2, uint32_t a3,
                                     uint32_t b0, uint32_t b1){
    asm volatile(
        "mma.sync.aligned.m16n8k8.row.col.f32.tf32.tf32.f32 "
        "{%0,%1,%2,%3}, {%4,%5,%6,%7}, {%8,%9}, {%0,%1,%2,%3};"
        : "+f"(c[0]), "+f"(c[1]), "+f"(c[2]), "+f"(c[3])
        : "r"(a0), "r"(a1), "r"(a2), "r"(a3), "r"(b0), "r"(b1));
}

// ------------------------- active-flag kernel ------------------------------
__global__ void __launch_bounds__(256)
active_kernel(const float* __restrict__ mask){
    int w    = blockIdx.x * 8 + (threadIdx.x >> 5);
    int lane = threadIdx.x & 31;
    int n    = w / (NB*NB);
    int rem  = w - n * (NB*NB);
    int bi   = rem / NB;
    int bj   = rem - bi * NB;
    float m = -1e30f;
#pragma unroll
    for (int i = 0; i < 8; i++){
        int e = lane + 32*i, rr = e >> 4, cc = e & 15;
        m = fmaxf(m, mask[((size_t)n*HIN + bi*14 + rr)*WIN + (bj*14 + cc)]);
    }
#pragma unroll
    for (int off = 16; off; off >>= 1)
        m = fmaxf(m, __shfl_xor_sync(0xffffffffu, m, off));
    if (lane == 0) d_active[w] = (m > 0.5f) ? 1.0f : 0.0f;
}

// ----------------------------- conv kernel ---------------------------------
extern __shared__ char smem[];

__global__ void __launch_bounds__(256, 2)
conv_mma(const float* __restrict__ x, const float* __restrict__ kern,
         const float* __restrict__ bias, float* __restrict__ out){
    const int tid  = threadIdx.x;
    const int wid  = tid >> 5;
    const int lane = tid & 31;
    const int g    = lane >> 2;       // groupID (0..7)
    const int t4   = lane & 3;        // threadID_in_group

    const int c0 = blockIdx.x * TCOLS;         // 0..480 (16 bands)
    const int R0 = blockIdx.y * TROWS;         // 0..496 (63 chunks)
    const int n  = blockIdx.z;

    uint32_t* xs = (uint32_t*)smem;            // tf32 bit patterns
    char*     ws = smem + W_OFF;

    // ---- stage weights in per-lane fragment order, XOR-swizzled 16B slots --
    // element e (0..31) of lane: nf=e>>3, s=(e>>1)&3, rg=e&1
    //   k = s*8 + t4 + rg*4 (ci), nn = nf*8 + g (cout)
    // slot addr: lane*128 + ((e>>2) ^ (lane&7))*16 + (e&3)*4
    for (int t = wid; t < 9; t += 8){
        const float* kt = kern + t * 1024;     // [ci][co]
        char* base = ws + t * 4096 + lane * 128;
#pragma unroll
        for (int e = 0; e < 32; e++){
            int nf = e >> 3, s = (e >> 1) & 3, rg = e & 1;
            int k  = s*8 + t4 + rg*4;
            int nn = nf*8 + g;
            *(uint32_t*)(base + (((e>>2) ^ (lane&7))*16) + (e&3)*4)
                = cvt_tf32(kt[k*32 + nn]);
        }
    }

    // ---- stage x tile: 10x34 pixels, ci permuted (ci' = (ci&3)*8 + ci>>2),
    //      pixel stride 36 floats ----
    for (int e = tid; e < XR*XC; e += 256){
        int tr = e / XC, tc = e - tr*XC;
        int hh = R0 + tr;                      // always < 506
        int wc = c0 + tc;
        uint32_t* dst = xs + e * PXF;
        if (wc < WIN){
            const float4* src = (const float4*)(x + (((size_t)n*HIN + hh)*WIN + wc)*CIN);
#pragma unroll
            for (int j = 0; j < 8; j++){
                float4 v = src[j];             // ci = 4j .. 4j+3
                dst[j]      = cvt_tf32(v.x);   // ci' = 0*8 + j
                dst[8 + j]  = cvt_tf32(v.y);
                dst[16 + j] = cvt_tf32(v.z);
                dst[24 + j] = cvt_tf32(v.w);
            }
        } else {
#pragma unroll
            for (int j = 0; j < 32; j++) dst[j] = 0u;
        }
    }
    __syncthreads();

    // ---- mainloop: warp = output row R0+wid, cols c0..c0+31 ----
    float acc[2][4][4];
#pragma unroll
    for (int f = 0; f < 2; f++)
#pragma unroll
        for (int nf = 0; nf < 4; nf++)
#pragma unroll
            for (int i = 0; i < 4; i++) acc[f][nf][i] = 0.0f;

#pragma unroll
    for (int dr = 0; dr < 3; dr++){
        const char* xrow = (const char*)xs + ((wid + dr) * XC) * (PXF*4);
#pragma unroll
        for (int dc = 0; dc < 3; dc++){
            // B fragments: 8 x LDS.128, conflict-free via XOR swizzle
            uint32_t fb[32];
            const char* wt = ws + (dr*3 + dc) * 4096 + lane * 128;
#pragma unroll
            for (int q = 0; q < 8; q++)
                *(uint4*)&fb[q*4] = *(const uint4*)(wt + ((q ^ (lane&7)) * 16));

#pragma unroll
            for (int f = 0; f < 2; f++){
                const char* pa = xrow + (f*16 + dc) * (PXF*4) + t4 * 32;
                uint4 lo0 = *(const uint4*)(pa + g * (PXF*4));
                uint4 lo1 = *(const uint4*)(pa + g * (PXF*4) + 16);
                uint4 hi0 = *(const uint4*)(pa + (g+8) * (PXF*4));
                uint4 hi1 = *(const uint4*)(pa + (g+8) * (PXF*4) + 16);
                uint32_t alo[8] = {lo0.x, lo0.y, lo0.z, lo0.w,
                                   lo1.x, lo1.y, lo1.z, lo1.w};
                uint32_t ahi[8] = {hi0.x, hi0.y, hi0.z, hi0.w,
                                   hi1.x, hi1.y, hi1.z, hi1.w};
#pragma unroll
                for (int s = 0; s < 4; s++){
                    uint32_t a0 = alo[2*s],   a1 = ahi[2*s];
                    uint32_t a2 = alo[2*s+1], a3 = ahi[2*s+1];
#pragma unroll
                    for (int nf = 0; nf < 4; nf++)
                        mma8(acc[f][nf], a0, a1, a2, a3,
                             fb[nf*8 + s*2], fb[nf*8 + s*2 + 1]);
                }
            }
        }
    }

    // ---- epilogue: (+bias) * active, coalesced STG.64 ----
    const int row = R0 + wid;                  // < 504 always
    const int rb  = (row / 14) * NB;
    const float* act = d_active + n * (NB*NB);
    float2 bv[4];
#pragma unroll
    for (int nf = 0; nf < 4; nf++)
        bv[nf] = *(const float2*)(bias + nf*8 + 2*t4);

    float* obase = out + (((size_t)n*OHW + row)*OHW) * CIN;
#pragma unroll
    for (int f = 0; f < 2; f++){
#pragma unroll
        for (int h = 0; h < 2; h++){
            int col = c0 + f*16 + g + h*8;
            if (col < OHW){
                float fa = act[rb + col/14];
                float* op = obase + (size_t)col * CIN + 2*t4;
#pragma unroll
                for (int nf = 0; nf < 4; nf++){
                    float2 v;
                    v.x = (acc[f][nf][h*2 + 0] + bv[nf].x) * fa;
                    v.y = (acc[f][nf][h*2 + 1] + bv[nf].y) * fa;
                    *(float2*)(op + nf*8) = v;
                }
            }
        }
    }
}

// ------------------------------- launch ------------------------------------
extern "C" void kernel_launch(void* const* d_in, const int* in_sizes, int n_in,
                              void* d_out, int out_size){
    const float* x    = (const float*)d_in[0];
    const float* mask = (const float*)d_in[1];
    const float* kern = (const float*)d_in[2];
    const float* bias = (const float*)d_in[3];
    float* out = (float*)d_out;

    active_kernel<<<1296, 256>>>(mask);

    cudaFuncSetAttribute(conv_mma, cudaFuncAttributeMaxDynamicSharedMemorySize,
                         SMEM_BYTES);
    dim3 grid(16, 63, NIMG);    // col bands x row chunks x images
    conv_mma<<<grid, 256, SMEM_BYTES>>>(x, kern, bias, out);
}

// round 7
// speedup vs baseline: 3.8607x; 1.1855x over previous
#include <cuda_runtime.h>
#include <cstdint>

// ---------------------------------------------------------------------------
// SparseConv2D == dense VALID 3x3 conv (R3 derivation) * per-14x14-block
// active flag.  mma.sync m16n8k8 tf32 implicit GEMM.
// R6: B amortized over 4 m-frags/warp (0.375 LDS.128/mma), identity ci layout
// -> vectorized conflict-free staging, 2 CTAs/SM.
// ---------------------------------------------------------------------------

#define NIMG 8
#define HIN  506
#define WIN  506
#define CIN  32
#define OHW  504
#define NB   36

#define TROWS 12              // output rows per CTA (6 warps x 2 rows)
#define TCOLS 32              // output cols per CTA
#define XR    14              // input rows in tile
#define XC    34              // input cols in tile
#define PXF   36              // floats per pixel slot (144 B; odd/4 -> no conflicts)
#define XS_BYTES (XR * XC * PXF * 4)          // 68544
#define W_OFF    XS_BYTES
#define SMEM_BYTES (W_OFF + 9 * 4096)         // 105408 -> 2 CTAs/SM

#define THREADS 192

__device__ float d_active[NIMG * NB * NB];

// ------------------------------ helpers ------------------------------------
__device__ __forceinline__ uint32_t cvt_tf32(float f){
    uint32_t u; asm("cvt.rna.tf32.f32 %0, %1;" : "=r"(u) : "f"(f)); return u;
}
__device__ __forceinline__ void mma8(float* c,
                                     uint32_t a0, uint32_t a1, uint32_t a2, uint32_t a3,
                                     uint32_t b0, uint32_t b1){
    asm volatile(
        "mma.sync.aligned.m16n8k8.row.col.f32.tf32.tf32.f32 "
        "{%0,%1,%2,%3}, {%4,%5,%6,%7}, {%8,%9}, {%0,%1,%2,%3};"
        : "+f"(c[0]), "+f"(c[1]), "+f"(c[2]), "+f"(c[3])
        : "r"(a0), "r"(a1), "r"(a2), "r"(a3), "r"(b0), "r"(b1));
}

// ------------------------- active-flag kernel ------------------------------
__global__ void __launch_bounds__(256)
active_kernel(const float* __restrict__ mask){
    int w    = blockIdx.x * 8 + (threadIdx.x >> 5);
    int lane = threadIdx.x & 31;
    int n    = w / (NB*NB);
    int rem  = w - n * (NB*NB);
    int bi   = rem / NB;
    int bj   = rem - bi * NB;
    float m = -1e30f;
#pragma unroll
    for (int i = 0; i < 8; i++){
        int e = lane + 32*i, rr = e >> 4, cc = e & 15;
        m = fmaxf(m, mask[((size_t)n*HIN + bi*14 + rr)*WIN + (bj*14 + cc)]);
    }
#pragma unroll
    for (int off = 16; off; off >>= 1)
        m = fmaxf(m, __shfl_xor_sync(0xffffffffu, m, off));
    if (lane == 0) d_active[w] = (m > 0.5f) ? 1.0f : 0.0f;
}

// ----------------------------- conv kernel ---------------------------------
extern __shared__ char smem[];

__global__ void __launch_bounds__(THREADS, 2)
conv_mma(const float* __restrict__ x, const float* __restrict__ kern,
         const float* __restrict__ bias, float* __restrict__ out){
    const int tid  = threadIdx.x;
    const int wid  = tid >> 5;        // 0..5
    const int lane = tid & 31;
    const int g    = lane >> 2;       // groupID (0..7)
    const int t4   = lane & 3;        // threadID_in_group

    const int c0 = blockIdx.x * TCOLS;         // 0..480 (16 bands)
    const int R0 = blockIdx.y * TROWS;         // 0..492 (42 chunks, exact)
    const int n  = blockIdx.z;

    uint32_t* xs = (uint32_t*)smem;            // tf32 bits, identity ci layout
    char*     ws = smem + W_OFF;

    // ---- stage weights in per-lane fragment order, XOR-swizzled 16B slots.
    // slot e of lane: nf=e>>3, s=(e>>1)&3, rg=e&1; holds
    //   w[ci = t4*8 + 2*s + rg][cout = nf*8 + g]   (identity-layout pairing)
    for (int t = wid; t < 9; t += 6){
        const float* kt = kern + t * 1024;     // [ci][co]
        char* base = ws + t * 4096 + lane * 128;
#pragma unroll
        for (int e = 0; e < 32; e++){
            int nf = e >> 3, s = (e >> 1) & 3, rg = e & 1;
            int k  = t4*8 + 2*s + rg;
            int nn = nf*8 + g;
            *(uint32_t*)(base + (((e>>2) ^ (lane&7))*16) + (e&3)*4)
                = cvt_tf32(kt[k*32 + nn]);
        }
    }

    // ---- stage x tile: 14x34 pixels, identity ci, pixel stride 36 floats.
    // LDG.128 -> cvt -> STS.128, conflict-free (addr/16 mod 8 = (e*9+j)%8).
    for (int e = tid; e < XR*XC; e += THREADS){
        int tr = e / XC, tc = e - tr*XC;
        int wc = c0 + tc;                       // row R0+tr always < 506
        uint4* dst = (uint4*)(xs + e * PXF);
        if (wc < WIN){
            const float4* src = (const float4*)(x + (((size_t)n*HIN + (R0+tr))*WIN + wc)*CIN);
#pragma unroll
            for (int j = 0; j < 8; j++){
                float4 v = src[j];
                dst[j] = make_uint4(cvt_tf32(v.x), cvt_tf32(v.y),
                                    cvt_tf32(v.z), cvt_tf32(v.w));
            }
        } else {
#pragma unroll
            for (int j = 0; j < 8; j++) dst[j] = make_uint4(0u,0u,0u,0u);
        }
    }
    __syncthreads();

    // ---- mainloop: warp = out rows R0+2*wid, +1, cols c0..c0+31 ----
    // acc[f][nf][4]: f = (rowInPair<<1 | colHalf) m-frags, nf = cout/8
    float acc[4][4][4];
#pragma unroll
    for (int f = 0; f < 4; f++)
#pragma unroll
        for (int nf = 0; nf < 4; nf++)
#pragma unroll
            for (int i = 0; i < 4; i++) acc[f][nf][i] = 0.0f;

    const int rowb = wid * 2;
    for (int dr = 0; dr < 3; dr++){
        for (int dc = 0; dc < 3; dc++){
            // B fragments: 8 LDS.128, conflict-free, reused by 4 m-frags
            uint32_t fb[32];
            const char* wt = ws + (dr*3 + dc) * 4096 + lane * 128;
#pragma unroll
            for (int q = 0; q < 8; q++)
                *(uint4*)&fb[q*4] = *(const uint4*)(wt + ((q ^ (lane&7)) * 16));

#pragma unroll
            for (int f = 0; f < 4; f++){
                const int trow = rowb + (f >> 1) + dr;
                const int coff = (f & 1) * 16 + dc;
                const char* pa = (const char*)xs + (trow*XC + coff) * (PXF*4) + t4*32;
                uint4 lo0 = *(const uint4*)(pa + g * (PXF*4));
                uint4 lo1 = *(const uint4*)(pa + g * (PXF*4) + 16);
                uint4 hi0 = *(const uint4*)(pa + (g+8) * (PXF*4));
                uint4 hi1 = *(const uint4*)(pa + (g+8) * (PXF*4) + 16);
                uint32_t alo[8] = {lo0.x, lo0.y, lo0.z, lo0.w,
                                   lo1.x, lo1.y, lo1.z, lo1.w};
                uint32_t ahi[8] = {hi0.x, hi0.y, hi0.z, hi0.w,
                                   hi1.x, hi1.y, hi1.z, hi1.w};
#pragma unroll
                for (int s = 0; s < 4; s++){
                    uint32_t a0 = alo[2*s],   a1 = ahi[2*s];
                    uint32_t a2 = alo[2*s+1], a3 = ahi[2*s+1];
#pragma unroll
                    for (int nf = 0; nf < 4; nf++)
                        mma8(acc[f][nf], a0, a1, a2, a3,
                             fb[nf*8 + s*2], fb[nf*8 + s*2 + 1]);
                }
            }
        }
    }

    // ---- epilogue: (+bias) * active, STG.64, rows always in-bounds ----
    const float* act = d_active + n * (NB*NB);
    float2 bv[4];
#pragma unroll
    for (int nf = 0; nf < 4; nf++)
        bv[nf] = *(const float2*)(bias + nf*8 + 2*t4);

#pragma unroll
    for (int f = 0; f < 4; f++){
        const int row = R0 + rowb + (f >> 1);
        const int rb  = (row / 14) * NB;
        float* obase = out + (((size_t)n*OHW + row)*OHW) * CIN;
#pragma unroll
        for (int h = 0; h < 2; h++){
            int col = c0 + (f & 1)*16 + g + h*8;
            if (col < OHW){
                float fa = act[rb + col/14];
                float* op = obase + (size_t)col * CIN + 2*t4;
#pragma unroll
                for (int nf = 0; nf < 4; nf++){
                    float2 v;
                    v.x = (acc[f][nf][h*2 + 0] + bv[nf].x) * fa;
                    v.y = (acc[f][nf][h*2 + 1] + bv[nf].y) * fa;
                    *(float2*)(op + nf*8) = v;
                }
            }
        }
    }
}

// ------------------------------- launch ------------------------------------
extern "C" void kernel_launch(void* const* d_in, const int* in_sizes, int n_in,
                              void* d_out, int out_size){
    const float* x    = (const float*)d_in[0];
    const float* mask = (const float*)d_in[1];
    const float* kern = (const float*)d_in[2];
    const float* bias = (const float*)d_in[3];
    float* out = (float*)d_out;

    active_kernel<<<1296, 256>>>(mask);

    cudaFuncSetAttribute(conv_mma, cudaFuncAttributeMaxDynamicSharedMemorySize,
                         SMEM_BYTES);
    dim3 grid(16, 42, NIMG);    // col bands x row chunks x images
    conv_mma<<<grid, THREADS, SMEM_BYTES>>>(x, kern, bias, out);
}